// round 4
// baseline (speedup 1.0000x reference)
#include <cuda_runtime.h>
#include <cuda_fp8.h>
#include <cstdint>

#define DIM 2048
#define NB  (DIM / 32)   // 64 scale blocks per row

// ---------------- scratch (device globals: no allocation allowed) ----------------
__device__ uint8_t g_xq[DIM * DIM];   // x quantized e4m3
__device__ uint8_t g_wq[DIM * DIM];   // w quantized e4m3
__device__ float   g_sx[DIM * NB];    // x block scales
__device__ float   g_sw[DIM * NB];    // w block scales

// ---------------- fused quantizer: 8 threads per 32-elem block ----------------
__global__ void __launch_bounds__(256) quant2_kernel(
        const float* __restrict__ x, const float* __restrict__ w,
        uint8_t* __restrict__ xq, uint8_t* __restrict__ wq,
        float* __restrict__ sx, float* __restrict__ sw) {
    const int gtid = blockIdx.x * blockDim.x + threadIdx.x;
    const int half = DIM * DIM / 4;                 // float4 count per tensor
    const bool isW = gtid >= half;
    const int t = isW ? gtid - half : gtid;
    const float4 v = (isW ? reinterpret_cast<const float4*>(w)
                          : reinterpret_cast<const float4*>(x))[t];
    float m = fmaxf(fmaxf(fabsf(v.x), fabsf(v.y)), fmaxf(fabsf(v.z), fabsf(v.w)));
    m = fmaxf(m, __shfl_xor_sync(0xFFFFFFFFu, m, 1));
    m = fmaxf(m, __shfl_xor_sync(0xFFFFFFFFu, m, 2));
    m = fmaxf(m, __shfl_xor_sync(0xFFFFFFFFu, m, 4));
    const float s = fmaxf(__fdiv_rn(m, 448.0f), 1e-30f);

    uint32_t pk = 0;
    const float e[4] = {v.x, v.y, v.z, v.w};
#pragma unroll
    for (int j = 0; j < 4; j++) {
        float qv = __fdiv_rn(e[j], s);              // RN div, matches jnp
        pk |= ((uint32_t)(uint8_t)__nv_cvt_float_to_fp8(qv, __NV_SATFINITE, __NV_E4M3)) << (8 * j);
    }
    reinterpret_cast<uint32_t*>(isW ? wq : xq)[t] = pk;
    if ((t & 7) == 0) (isW ? sw : sx)[t >> 3] = s;
}

// ---------------- GEMM: CTA 128x128, 8 warps of 64x32, 2 CTAs/SM ----------------
// Smem stage: A 16KB | B 16KB | SX 2KB | SW 2KB => 36864 B; two stages = 73728 B.
static constexpr int STG      = 36864;
static constexpr int OFF_B    = 16384;
static constexpr int OFF_SX   = 32768;
static constexpr int OFF_SW   = 34816;
static constexpr int SMEM_TOT = 2 * STG;

#define SWZ_OFF(r, c) (((r) * 128) + ((((c) ^ ((r) & 7)) & 7) << 4))

__device__ __forceinline__ void cp16(uint32_t saddr, const void* gptr) {
    asm volatile("cp.async.cg.shared.global [%0], [%1], 16;"
                 :: "r"(saddr), "l"(__cvta_generic_to_global(gptr)));
}
__device__ __forceinline__ void cp16ca(uint32_t saddr, const void* gptr) {
    asm volatile("cp.async.ca.shared.global [%0], [%1], 16;"
                 :: "r"(saddr), "l"(__cvta_generic_to_global(gptr)));
}

__device__ __forceinline__ unsigned long long pk2(float lo, float hi) {
    unsigned long long r;
    asm("mov.b64 %0, {%1, %2};" : "=l"(r) : "f"(lo), "f"(hi));
    return r;
}
__device__ __forceinline__ unsigned long long mul2(unsigned long long a, unsigned long long b) {
    unsigned long long r;
    asm("mul.rn.f32x2 %0, %1, %2;" : "=l"(r) : "l"(a), "l"(b));
    return r;
}
__device__ __forceinline__ unsigned long long fma2(unsigned long long a, unsigned long long b,
                                                   unsigned long long c) {
    unsigned long long r;
    asm("fma.rn.f32x2 %0, %1, %2, %3;" : "=l"(r) : "l"(a), "l"(b), "l"(c));
    return r;
}

__global__ void __launch_bounds__(256, 2)
gemm_kernel(const float* __restrict__ bias, float* __restrict__ out) {
    extern __shared__ char smem[];
    const uint32_t sbase = (uint32_t)__cvta_generic_to_shared(smem);
    const int tid  = threadIdx.x;
    const int lane = tid & 31, warp = tid >> 5;
    const int m0 = blockIdx.y * 128, n0 = blockIdx.x * 128;
    const int wm0 = (warp >> 2) * 64, wn0 = (warp & 3) * 32;

    // acc[mt][nt][0] = rows r0, cols {cj,cj+1}; [1] = rows r0+8
    unsigned long long acc[4][4][2];
#pragma unroll
    for (int i = 0; i < 4; i++)
#pragma unroll
        for (int j = 0; j < 4; j++) { acc[i][j][0] = 0ull; acc[i][j][1] = 0ull; }

    auto load_stage = [&](int kc, int st) {
        const uint32_t sb = sbase + st * STG;
#pragma unroll
        for (int i = 0; i < 4; i++) {
            const int idx = tid * 4 + i;          // 1024 chunks of 16B
            const int r = idx >> 3, c = idx & 7;
            cp16(sb + SWZ_OFF(r, c), g_xq + (size_t)(m0 + r) * DIM + kc * 128 + c * 16);
            cp16(sb + OFF_B + SWZ_OFF(r, c), g_wq + (size_t)(n0 + r) * DIM + kc * 128 + c * 16);
        }
        if (tid < 128)
            cp16ca(sb + OFF_SX + tid * 16, g_sx + (size_t)(m0 + tid) * NB + kc * 4);
        else {
            const int t = tid - 128;
            cp16ca(sb + OFF_SW + t * 16, g_sw + (size_t)(n0 + t) * NB + kc * 4);
        }
    };

    load_stage(0, 0);
    asm volatile("cp.async.commit_group;" ::: "memory");

#pragma unroll 1
    for (int kc = 0; kc < 16; kc++) {
        const int st = kc & 1;
        if (kc + 1 < 16) load_stage(kc + 1, st ^ 1);
        asm volatile("cp.async.commit_group;" ::: "memory");
        asm volatile("cp.async.wait_group 1;" ::: "memory");
        __syncthreads();

        const uint32_t sb = sbase + st * STG;
        const char* ss = smem + st * STG;

#pragma unroll
        for (int b = 0; b < 4; b++) {   // 4 scale-blocks (K=32) per 128B chunk
            // A fragments: 4 m-tiles of 16 rows
            uint32_t af[4][4];
#pragma unroll
            for (int mt = 0; mt < 4; mt++) {
                const int r = wm0 + mt * 16 + (lane & 15);
                const int c = 2 * b + (lane >> 4);
                asm volatile("ldmatrix.sync.aligned.m8n8.x4.shared.b16 {%0,%1,%2,%3}, [%4];"
                             : "=r"(af[mt][0]), "=r"(af[mt][1]), "=r"(af[mt][2]), "=r"(af[mt][3])
                             : "r"(sb + SWZ_OFF(r, c)));
            }
            // packed A-row scales for this block
            unsigned long long sxaa[4], sxbb[4];
#pragma unroll
            for (int mt = 0; mt < 4; mt++) {
                const int r = wm0 + mt * 16 + (lane >> 2);
                float a  = *reinterpret_cast<const float*>(ss + OFF_SX + r * 16 + b * 4);
                float bb = *reinterpret_cast<const float*>(ss + OFF_SX + (r + 8) * 16 + b * 4);
                sxaa[mt] = pk2(a, a);
                sxbb[mt] = pk2(bb, bb);
            }
#pragma unroll
            for (int nt = 0; nt < 4; nt++) {
                uint32_t bf0, bf1;
                {
                    const int r = wn0 + nt * 8 + (lane & 7);
                    const int c = 2 * b + ((lane >> 3) & 1);
                    asm volatile("ldmatrix.sync.aligned.m8n8.x2.shared.b16 {%0,%1}, [%2];"
                                 : "=r"(bf0), "=r"(bf1)
                                 : "r"(sb + OFF_B + SWZ_OFF(r, c)));
                }
                const int cj = wn0 + nt * 8 + ((lane & 3) << 1);
                const unsigned long long sw01 =
                    pk2(*reinterpret_cast<const float*>(ss + OFF_SW + cj * 16 + b * 4),
                        *reinterpret_cast<const float*>(ss + OFF_SW + (cj + 1) * 16 + b * 4));
#pragma unroll
                for (int mt = 0; mt < 4; mt++) {
                    float d0, d1, d2, d3;
                    asm volatile(
                        "mma.sync.aligned.m16n8k32.row.col.f32.e4m3.e4m3.f32 "
                        "{%0,%1,%2,%3}, {%4,%5,%6,%7}, {%8,%9}, {%10,%11,%12,%13};"
                        : "=f"(d0), "=f"(d1), "=f"(d2), "=f"(d3)
                        : "r"(af[mt][0]), "r"(af[mt][1]), "r"(af[mt][2]), "r"(af[mt][3]),
                          "r"(bf0), "r"(bf1),
                          "f"(0.f), "f"(0.f), "f"(0.f), "f"(0.f));
                    acc[mt][nt][0] = fma2(mul2(sxaa[mt], sw01), pk2(d0, d1), acc[mt][nt][0]);
                    acc[mt][nt][1] = fma2(mul2(sxbb[mt], sw01), pk2(d2, d3), acc[mt][nt][1]);
                }
            }
        }
        __syncthreads();
    }

    // ---- epilogue: add bias, store fp32 ----
#pragma unroll
    for (int mt = 0; mt < 4; mt++) {
        const int r0 = m0 + wm0 + mt * 16 + (lane >> 2);
#pragma unroll
        for (int nt = 0; nt < 4; nt++) {
            const int cj = n0 + wn0 + nt * 8 + ((lane & 3) << 1);
            const float2 bz = *reinterpret_cast<const float2*>(bias + cj);
            const unsigned long long a0 = acc[mt][nt][0], a1 = acc[mt][nt][1];
            float2 o0 = make_float2(__uint_as_float((uint32_t)a0) + bz.x,
                                    __uint_as_float((uint32_t)(a0 >> 32)) + bz.y);
            float2 o1 = make_float2(__uint_as_float((uint32_t)a1) + bz.x,
                                    __uint_as_float((uint32_t)(a1 >> 32)) + bz.y);
            *reinterpret_cast<float2*>(out + (size_t)r0 * DIM + cj) = o0;
            *reinterpret_cast<float2*>(out + (size_t)(r0 + 8) * DIM + cj) = o1;
        }
    }
}

// ---------------- launch ----------------
extern "C" void kernel_launch(void* const* d_in, const int* in_sizes, int n_in,
                              void* d_out, int out_size) {
    const float* x    = (const float*)d_in[0];
    const float* w    = (const float*)d_in[1];
    const float* bias = (const float*)d_in[2];
    float* out = (float*)d_out;

    void *xq, *wq, *sx, *sw;
    cudaGetSymbolAddress(&xq, g_xq);
    cudaGetSymbolAddress(&wq, g_wq);
    cudaGetSymbolAddress(&sx, g_sx);
    cudaGetSymbolAddress(&sw, g_sw);

    cudaFuncSetAttribute(gemm_kernel, cudaFuncAttributeMaxDynamicSharedMemorySize, SMEM_TOT);

    const int nthreads = 2 * DIM * DIM / 4;         // 8 threads per 32-elem block, 2 tensors
    quant2_kernel<<<nthreads / 256, 256>>>(x, w, (uint8_t*)xq, (uint8_t*)wq,
                                           (float*)sx, (float*)sw);
    gemm_kernel<<<dim3(16, 16), 256, SMEM_TOT>>>(bias, out);
}

// round 5
// speedup vs baseline: 1.5511x; 1.5511x over previous
#include <cuda_runtime.h>
#include <cuda_fp8.h>
#include <cstdint>

#define DIM 2048
#define NB  (DIM / 32)   // 64 scale blocks per row

// ---------------- scratch (device globals: no allocation allowed) ----------------
__device__ uint8_t g_xq[DIM * DIM];   // x quantized e4m3
__device__ uint8_t g_wq[DIM * DIM];   // w quantized e4m3
__device__ float   g_sx[DIM * NB];    // x block scales
__device__ float   g_sw[DIM * NB];    // w block scales

// ---------------- fused quantizer: 8 threads per 32-elem block ----------------
__global__ void __launch_bounds__(256) quant2_kernel(
        const float* __restrict__ x, const float* __restrict__ w,
        uint8_t* __restrict__ xq, uint8_t* __restrict__ wq,
        float* __restrict__ sx, float* __restrict__ sw) {
    const int gtid = blockIdx.x * blockDim.x + threadIdx.x;
    const int half = DIM * DIM / 4;                 // float4 count per tensor
    const bool isW = gtid >= half;
    const int t = isW ? gtid - half : gtid;
    const float4 v = (isW ? reinterpret_cast<const float4*>(w)
                          : reinterpret_cast<const float4*>(x))[t];
    float m = fmaxf(fmaxf(fabsf(v.x), fabsf(v.y)), fmaxf(fabsf(v.z), fabsf(v.w)));
    m = fmaxf(m, __shfl_xor_sync(0xFFFFFFFFu, m, 1));
    m = fmaxf(m, __shfl_xor_sync(0xFFFFFFFFu, m, 2));
    m = fmaxf(m, __shfl_xor_sync(0xFFFFFFFFu, m, 4));
    const float s = fmaxf(__fdiv_rn(m, 448.0f), 1e-30f);

    uint32_t pk = 0;
    const float e[4] = {v.x, v.y, v.z, v.w};
#pragma unroll
    for (int j = 0; j < 4; j++) {
        float qv = __fdiv_rn(e[j], s);              // RN div, matches jnp
        pk |= ((uint32_t)(uint8_t)__nv_cvt_float_to_fp8(qv, __NV_SATFINITE, __NV_E4M3)) << (8 * j);
    }
    reinterpret_cast<uint32_t*>(isW ? wq : xq)[t] = pk;
    if ((t & 7) == 0) (isW ? sw : sx)[t >> 3] = s;
}

// ---------------- GEMM: CTA 128x128, 8 warps of 64x32, 3-stage cp.async ----------------
// Stage: A 16KB | B 16KB | SX 2KB | SW 2KB => 36864 B; three stages = 110592 B.
static constexpr int STG      = 36864;
static constexpr int OFF_B    = 16384;
static constexpr int OFF_SX   = 32768;
static constexpr int OFF_SW   = 34816;
static constexpr int SMEM_TOT = 3 * STG;

#define SWZ_OFF(r, c) (((r) * 128) + ((((c) ^ ((r) & 7)) & 7) << 4))

__device__ __forceinline__ void cp16(uint32_t saddr, const void* gptr) {
    asm volatile("cp.async.cg.shared.global [%0], [%1], 16;"
                 :: "r"(saddr), "l"(__cvta_generic_to_global(gptr)));
}
__device__ __forceinline__ void cp16ca(uint32_t saddr, const void* gptr) {
    asm volatile("cp.async.ca.shared.global [%0], [%1], 16;"
                 :: "r"(saddr), "l"(__cvta_generic_to_global(gptr)));
}

__device__ __forceinline__ unsigned long long pk2(float lo, float hi) {
    unsigned long long r;
    asm("mov.b64 %0, {%1, %2};" : "=l"(r) : "f"(lo), "f"(hi));
    return r;
}
__device__ __forceinline__ unsigned long long mul2(unsigned long long a, unsigned long long b) {
    unsigned long long r;
    asm("mul.rn.f32x2 %0, %1, %2;" : "=l"(r) : "l"(a), "l"(b));
    return r;
}
__device__ __forceinline__ unsigned long long fma2(unsigned long long a, unsigned long long b,
                                                   unsigned long long c) {
    unsigned long long r;
    asm("fma.rn.f32x2 %0, %1, %2, %3;" : "=l"(r) : "l"(a), "l"(b), "l"(c));
    return r;
}
__device__ __forceinline__ float fsel(float4 v, int b) {
    return b == 0 ? v.x : b == 1 ? v.y : b == 2 ? v.z : v.w;
}

__global__ void __launch_bounds__(256, 1)
gemm_kernel(const float* __restrict__ bias, float* __restrict__ out) {
    extern __shared__ char smem[];
    const uint32_t sbase = (uint32_t)__cvta_generic_to_shared(smem);
    const int tid  = threadIdx.x;
    const int lane = tid & 31, warp = tid >> 5;
    const int m0 = blockIdx.y * 128, n0 = blockIdx.x * 128;
    const int wm0 = (warp >> 2) * 64, wn0 = (warp & 3) * 32;

    // acc[mt][nt][0] = rows r0, cols {cj,cj+1}; [1] = rows r0+8
    unsigned long long acc[4][4][2];
#pragma unroll
    for (int i = 0; i < 4; i++)
#pragma unroll
        for (int j = 0; j < 4; j++) { acc[i][j][0] = 0ull; acc[i][j][1] = 0ull; }

    auto load_stage = [&](int kc, int st) {
        const uint32_t sb = sbase + st * STG;
#pragma unroll
        for (int i = 0; i < 4; i++) {
            const int idx = tid * 4 + i;          // 1024 chunks of 16B
            const int r = idx >> 3, c = idx & 7;
            cp16(sb + SWZ_OFF(r, c), g_xq + (size_t)(m0 + r) * DIM + kc * 128 + c * 16);
            cp16(sb + OFF_B + SWZ_OFF(r, c), g_wq + (size_t)(n0 + r) * DIM + kc * 128 + c * 16);
        }
        if (tid < 128)
            cp16ca(sb + OFF_SX + tid * 16, g_sx + (size_t)(m0 + tid) * NB + kc * 4);
        else {
            const int t = tid - 128;
            cp16ca(sb + OFF_SW + t * 16, g_sw + (size_t)(n0 + t) * NB + kc * 4);
        }
    };

    load_stage(0, 0);
    asm volatile("cp.async.commit_group;" ::: "memory");
    load_stage(1, 1);
    asm volatile("cp.async.commit_group;" ::: "memory");

#pragma unroll 1
    for (int kc = 0; kc < 16; kc++) {
        const int st = kc - (kc / 3) * 3;          // kc % 3
        asm volatile("cp.async.wait_group 1;" ::: "memory");
        __syncthreads();
        if (kc + 2 < 16) {
            const int st2 = (kc + 2) - ((kc + 2) / 3) * 3;
            load_stage(kc + 2, st2);
        }
        asm volatile("cp.async.commit_group;" ::: "memory");

        const uint32_t sb = sbase + st * STG;
        const char* ss = smem + st * STG;

        // ---- hoisted scale loads: one float4 per row/col covers all 4 b ----
        float4 sxa4[4], sxb4[4];
#pragma unroll
        for (int mt = 0; mt < 4; mt++) {
            const int r = wm0 + mt * 16 + (lane >> 2);
            sxa4[mt] = *reinterpret_cast<const float4*>(ss + OFF_SX + r * 16);
            sxb4[mt] = *reinterpret_cast<const float4*>(ss + OFF_SX + (r + 8) * 16);
        }
        float4 sw40[4], sw41[4];
#pragma unroll
        for (int nt = 0; nt < 4; nt++) {
            const int cj = wn0 + nt * 8 + ((lane & 3) << 1);
            sw40[nt] = *reinterpret_cast<const float4*>(ss + OFF_SW + cj * 16);
            sw41[nt] = *reinterpret_cast<const float4*>(ss + OFF_SW + (cj + 1) * 16);
        }

#pragma unroll
        for (int b = 0; b < 4; b++) {   // 4 scale-blocks (K=32) per 128B chunk
            // ---- all fragments first: 4 A-ldmatrix.x4 + 2 B-ldmatrix.x4 ----
            uint32_t af[4][4];
#pragma unroll
            for (int mt = 0; mt < 4; mt++) {
                const int r = wm0 + mt * 16 + (lane & 15);
                const int c = 2 * b + (lane >> 4);
                asm volatile("ldmatrix.sync.aligned.m8n8.x4.shared.b16 {%0,%1,%2,%3}, [%4];"
                             : "=r"(af[mt][0]), "=r"(af[mt][1]), "=r"(af[mt][2]), "=r"(af[mt][3])
                             : "r"(sb + SWZ_OFF(r, c)));
            }
            uint32_t bf[4][2];
#pragma unroll
            for (int p = 0; p < 2; p++) {  // nt pair {2p, 2p+1}
                const int mlm = lane >> 3;   // matrix id 0..3
                const int r = wn0 + p * 16 + ((mlm >> 1) << 3) + (lane & 7);
                const int c = 2 * b + (mlm & 1);
                asm volatile("ldmatrix.sync.aligned.m8n8.x4.shared.b16 {%0,%1,%2,%3}, [%4];"
                             : "=r"(bf[2 * p][0]), "=r"(bf[2 * p][1]),
                               "=r"(bf[2 * p + 1][0]), "=r"(bf[2 * p + 1][1])
                             : "r"(sb + OFF_B + SWZ_OFF(r, c)));
            }
            // ---- packed scales for this b ----
            unsigned long long sxaa[4], sxbb[4], sw01[4];
#pragma unroll
            for (int mt = 0; mt < 4; mt++) {
                const float a = fsel(sxa4[mt], b), bb = fsel(sxb4[mt], b);
                sxaa[mt] = pk2(a, a);
                sxbb[mt] = pk2(bb, bb);
            }
#pragma unroll
            for (int nt = 0; nt < 4; nt++)
                sw01[nt] = pk2(fsel(sw40[nt], b), fsel(sw41[nt], b));

            // ---- 16 independent mmas + f32x2 scale-apply ----
#pragma unroll
            for (int nt = 0; nt < 4; nt++)
#pragma unroll
                for (int mt = 0; mt < 4; mt++) {
                    float d0, d1, d2, d3;
                    asm volatile(
                        "mma.sync.aligned.m16n8k32.row.col.f32.e4m3.e4m3.f32 "
                        "{%0,%1,%2,%3}, {%4,%5,%6,%7}, {%8,%9}, {%10,%11,%12,%13};"
                        : "=f"(d0), "=f"(d1), "=f"(d2), "=f"(d3)
                        : "r"(af[mt][0]), "r"(af[mt][1]), "r"(af[mt][2]), "r"(af[mt][3]),
                          "r"(bf[nt][0]), "r"(bf[nt][1]),
                          "f"(0.f), "f"(0.f), "f"(0.f), "f"(0.f));
                    acc[mt][nt][0] = fma2(mul2(sxaa[mt], sw01[nt]), pk2(d0, d1), acc[mt][nt][0]);
                    acc[mt][nt][1] = fma2(mul2(sxbb[mt], sw01[nt]), pk2(d2, d3), acc[mt][nt][1]);
                }
        }
    }

    // ---- epilogue: add bias, store fp32 ----
#pragma unroll
    for (int mt = 0; mt < 4; mt++) {
        const int r0 = m0 + wm0 + mt * 16 + (lane >> 2);
#pragma unroll
        for (int nt = 0; nt < 4; nt++) {
            const int cj = n0 + wn0 + nt * 8 + ((lane & 3) << 1);
            const float2 bz = *reinterpret_cast<const float2*>(bias + cj);
            const unsigned long long a0 = acc[mt][nt][0], a1 = acc[mt][nt][1];
            float2 o0 = make_float2(__uint_as_float((uint32_t)a0) + bz.x,
                                    __uint_as_float((uint32_t)(a0 >> 32)) + bz.y);
            float2 o1 = make_float2(__uint_as_float((uint32_t)a1) + bz.x,
                                    __uint_as_float((uint32_t)(a1 >> 32)) + bz.y);
            *reinterpret_cast<float2*>(out + (size_t)r0 * DIM + cj) = o0;
            *reinterpret_cast<float2*>(out + (size_t)(r0 + 8) * DIM + cj) = o1;
        }
    }
}

// ---------------- launch ----------------
extern "C" void kernel_launch(void* const* d_in, const int* in_sizes, int n_in,
                              void* d_out, int out_size) {
    const float* x    = (const float*)d_in[0];
    const float* w    = (const float*)d_in[1];
    const float* bias = (const float*)d_in[2];
    float* out = (float*)d_out;

    void *xq, *wq, *sx, *sw;
    cudaGetSymbolAddress(&xq, g_xq);
    cudaGetSymbolAddress(&wq, g_wq);
    cudaGetSymbolAddress(&sx, g_sx);
    cudaGetSymbolAddress(&sw, g_sw);

    cudaFuncSetAttribute(gemm_kernel, cudaFuncAttributeMaxDynamicSharedMemorySize, SMEM_TOT);

    const int nthreads = 2 * DIM * DIM / 4;         // 8 threads per 32-elem block, 2 tensors
    quant2_kernel<<<nthreads / 256, 256>>>(x, w, (uint8_t*)xq, (uint8_t*)wq,
                                           (float*)sx, (float*)sw);
    gemm_kernel<<<dim3(16, 16), 256, SMEM_TOT>>>(bias, out);
}

// round 6
// speedup vs baseline: 1.6210x; 1.0451x over previous
#include <cuda_runtime.h>
#include <cuda_fp8.h>
#include <cstdint>

#define DIM 2048
#define NB  (DIM / 32)   // 64 scale blocks per row

// ---------------- scratch (device globals: no allocation allowed) ----------------
__device__ uint8_t g_xq[DIM * DIM];   // x quantized e4m3
__device__ uint8_t g_wq[DIM * DIM];   // w quantized e4m3
__device__ float   g_sx[DIM * NB];    // x block scales
__device__ float   g_sw[DIM * NB];    // w block scales

// ---------------- fused quantizer: 8 threads per 32-elem block ----------------
__global__ void __launch_bounds__(256) quant2_kernel(
        const float* __restrict__ x, const float* __restrict__ w,
        uint8_t* __restrict__ xq, uint8_t* __restrict__ wq,
        float* __restrict__ sx, float* __restrict__ sw) {
    const int gtid = blockIdx.x * blockDim.x + threadIdx.x;
    const int half = DIM * DIM / 4;                 // float4 count per tensor
    const bool isW = gtid >= half;
    const int t = isW ? gtid - half : gtid;
    const float4 v = (isW ? reinterpret_cast<const float4*>(w)
                          : reinterpret_cast<const float4*>(x))[t];
    float m = fmaxf(fmaxf(fabsf(v.x), fabsf(v.y)), fmaxf(fabsf(v.z), fabsf(v.w)));
    m = fmaxf(m, __shfl_xor_sync(0xFFFFFFFFu, m, 1));
    m = fmaxf(m, __shfl_xor_sync(0xFFFFFFFFu, m, 2));
    m = fmaxf(m, __shfl_xor_sync(0xFFFFFFFFu, m, 4));
    const float s = fmaxf(__fdiv_rn(m, 448.0f), 1e-30f);

    uint32_t pk = 0;
    const float e[4] = {v.x, v.y, v.z, v.w};
#pragma unroll
    for (int j = 0; j < 4; j++) {
        float qv = __fdiv_rn(e[j], s);              // RN div, matches jnp
        pk |= ((uint32_t)(uint8_t)__nv_cvt_float_to_fp8(qv, __NV_SATFINITE, __NV_E4M3)) << (8 * j);
    }
    reinterpret_cast<uint32_t*>(isW ? wq : xq)[t] = pk;
    if ((t & 7) == 0) (isW ? sw : sx)[t >> 3] = s;
}

// ---------------- GEMM: CTA 128x128, 16 warps of 32x32, 3-stage cp.async ----------------
// Stage: A 16KB | B 16KB | SX 2KB | SW 2KB => 36864 B; three stages = 110592 B.
static constexpr int STG      = 36864;
static constexpr int OFF_B    = 16384;
static constexpr int OFF_SX   = 32768;
static constexpr int OFF_SW   = 34816;
static constexpr int SMEM_TOT = 3 * STG;

#define SWZ_OFF(r, c) (((r) * 128) + ((((c) ^ ((r) & 7)) & 7) << 4))

__device__ __forceinline__ void cp16(uint32_t saddr, const void* gptr) {
    asm volatile("cp.async.cg.shared.global [%0], [%1], 16;"
                 :: "r"(saddr), "l"(__cvta_generic_to_global(gptr)));
}
__device__ __forceinline__ void cp16ca(uint32_t saddr, const void* gptr) {
    asm volatile("cp.async.ca.shared.global [%0], [%1], 16;"
                 :: "r"(saddr), "l"(__cvta_generic_to_global(gptr)));
}

__device__ __forceinline__ unsigned long long pk2(float lo, float hi) {
    unsigned long long r;
    asm("mov.b64 %0, {%1, %2};" : "=l"(r) : "f"(lo), "f"(hi));
    return r;
}
__device__ __forceinline__ unsigned long long mul2(unsigned long long a, unsigned long long b) {
    unsigned long long r;
    asm("mul.rn.f32x2 %0, %1, %2;" : "=l"(r) : "l"(a), "l"(b));
    return r;
}
__device__ __forceinline__ unsigned long long fma2(unsigned long long a, unsigned long long b,
                                                   unsigned long long c) {
    unsigned long long r;
    asm("fma.rn.f32x2 %0, %1, %2, %3;" : "=l"(r) : "l"(a), "l"(b), "l"(c));
    return r;
}
__device__ __forceinline__ float fsel(float4 v, int b) {
    return b == 0 ? v.x : b == 1 ? v.y : b == 2 ? v.z : v.w;
}

__global__ void __launch_bounds__(512, 1)
gemm_kernel(const float* __restrict__ bias, float* __restrict__ out) {
    extern __shared__ char smem[];
    const uint32_t sbase = (uint32_t)__cvta_generic_to_shared(smem);
    const int tid  = threadIdx.x;
    const int lane = tid & 31, warp = tid >> 5;
    const int m0 = blockIdx.y * 128, n0 = blockIdx.x * 128;
    const int wm0 = (warp >> 2) * 32, wn0 = (warp & 3) * 32;   // 4x4 warp grid, 32x32 tiles

    // acc[mt][nt][0] = rows r0, cols {cj,cj+1}; [1] = rows r0+8
    unsigned long long acc[2][4][2];
#pragma unroll
    for (int i = 0; i < 2; i++)
#pragma unroll
        for (int j = 0; j < 4; j++) { acc[i][j][0] = 0ull; acc[i][j][1] = 0ull; }

    auto load_stage = [&](int kc, int st) {
        const uint32_t sb = sbase + st * STG;
#pragma unroll
        for (int i = 0; i < 2; i++) {             // 512 threads x 2 chunks = 1024
            const int idx = tid * 2 + i;
            const int r = idx >> 3, c = idx & 7;
            cp16(sb + SWZ_OFF(r, c), g_xq + (size_t)(m0 + r) * DIM + kc * 128 + c * 16);
            cp16(sb + OFF_B + SWZ_OFF(r, c), g_wq + (size_t)(n0 + r) * DIM + kc * 128 + c * 16);
        }
        if (tid < 128)
            cp16ca(sb + OFF_SX + tid * 16, g_sx + (size_t)(m0 + tid) * NB + kc * 4);
        else if (tid < 256) {
            const int t = tid - 128;
            cp16ca(sb + OFF_SW + t * 16, g_sw + (size_t)(n0 + t) * NB + kc * 4);
        }
    };

    load_stage(0, 0);
    asm volatile("cp.async.commit_group;" ::: "memory");
    load_stage(1, 1);
    asm volatile("cp.async.commit_group;" ::: "memory");

#pragma unroll 1
    for (int kc = 0; kc < 16; kc++) {
        const int st = kc - (kc / 3) * 3;          // kc % 3
        asm volatile("cp.async.wait_group 1;" ::: "memory");
        __syncthreads();
        if (kc + 2 < 16) {
            const int st2 = (kc + 2) - ((kc + 2) / 3) * 3;
            load_stage(kc + 2, st2);
        }
        asm volatile("cp.async.commit_group;" ::: "memory");

        const uint32_t sb = sbase + st * STG;
        const char* ss = smem + st * STG;

        // hoisted A-row scales (one float4 per row covers all 4 b)
        float4 sxa4[2], sxb4[2];
#pragma unroll
        for (int mt = 0; mt < 2; mt++) {
            const int r = wm0 + mt * 16 + (lane >> 2);
            sxa4[mt] = *reinterpret_cast<const float4*>(ss + OFF_SX + r * 16);
            sxb4[mt] = *reinterpret_cast<const float4*>(ss + OFF_SX + (r + 8) * 16);
        }

#pragma unroll
        for (int b = 0; b < 4; b++) {   // 4 scale-blocks (K=32) per 128B chunk
            // ---- fragments: 2 A-ldmatrix.x4 + 2 B-ldmatrix.x4 ----
            uint32_t af[2][4];
#pragma unroll
            for (int mt = 0; mt < 2; mt++) {
                const int r = wm0 + mt * 16 + (lane & 15);
                const int c = 2 * b + (lane >> 4);
                asm volatile("ldmatrix.sync.aligned.m8n8.x4.shared.b16 {%0,%1,%2,%3}, [%4];"
                             : "=r"(af[mt][0]), "=r"(af[mt][1]), "=r"(af[mt][2]), "=r"(af[mt][3])
                             : "r"(sb + SWZ_OFF(r, c)));
            }
            uint32_t bf[4][2];
#pragma unroll
            for (int p = 0; p < 2; p++) {  // covers nt {2p, 2p+1}
                const int mlm = lane >> 3;   // matrix id 0..3
                const int r = wn0 + p * 16 + ((mlm >> 1) << 3) + (lane & 7);
                const int c = 2 * b + (mlm & 1);
                asm volatile("ldmatrix.sync.aligned.m8n8.x4.shared.b16 {%0,%1,%2,%3}, [%4];"
                             : "=r"(bf[2 * p][0]), "=r"(bf[2 * p][1]),
                               "=r"(bf[2 * p + 1][0]), "=r"(bf[2 * p + 1][1])
                             : "r"(sb + OFF_B + SWZ_OFF(r, c)));
            }
            // ---- scales for this b ----
            unsigned long long sxaa[2], sxbb[2], sw01[4];
#pragma unroll
            for (int mt = 0; mt < 2; mt++) {
                const float a = fsel(sxa4[mt], b), bb = fsel(sxb4[mt], b);
                sxaa[mt] = pk2(a, a);
                sxbb[mt] = pk2(bb, bb);
            }
#pragma unroll
            for (int nt = 0; nt < 4; nt++) {
                const int cj = wn0 + nt * 8 + ((lane & 3) << 1);
                sw01[nt] = pk2(*reinterpret_cast<const float*>(ss + OFF_SW + cj * 16 + b * 4),
                               *reinterpret_cast<const float*>(ss + OFF_SW + (cj + 1) * 16 + b * 4));
            }

            // ---- 8 independent mmas + f32x2 scale-apply ----
#pragma unroll
            for (int nt = 0; nt < 4; nt++)
#pragma unroll
                for (int mt = 0; mt < 2; mt++) {
                    float d0, d1, d2, d3;
                    asm volatile(
                        "mma.sync.aligned.m16n8k32.row.col.f32.e4m3.e4m3.f32 "
                        "{%0,%1,%2,%3}, {%4,%5,%6,%7}, {%8,%9}, {%10,%11,%12,%13};"
                        : "=f"(d0), "=f"(d1), "=f"(d2), "=f"(d3)
                        : "r"(af[mt][0]), "r"(af[mt][1]), "r"(af[mt][2]), "r"(af[mt][3]),
                          "r"(bf[nt][0]), "r"(bf[nt][1]),
                          "f"(0.f), "f"(0.f), "f"(0.f), "f"(0.f));
                    acc[mt][nt][0] = fma2(mul2(sxaa[mt], sw01[nt]), pk2(d0, d1), acc[mt][nt][0]);
                    acc[mt][nt][1] = fma2(mul2(sxbb[mt], sw01[nt]), pk2(d2, d3), acc[mt][nt][1]);
                }
        }
    }

    // ---- epilogue: add bias, store fp32 ----
#pragma unroll
    for (int mt = 0; mt < 2; mt++) {
        const int r0 = m0 + wm0 + mt * 16 + (lane >> 2);
#pragma unroll
        for (int nt = 0; nt < 4; nt++) {
            const int cj = n0 + wn0 + nt * 8 + ((lane & 3) << 1);
            const float2 bz = *reinterpret_cast<const float2*>(bias + cj);
            const unsigned long long a0 = acc[mt][nt][0], a1 = acc[mt][nt][1];
            float2 o0 = make_float2(__uint_as_float((uint32_t)a0) + bz.x,
                                    __uint_as_float((uint32_t)(a0 >> 32)) + bz.y);
            float2 o1 = make_float2(__uint_as_float((uint32_t)a1) + bz.x,
                                    __uint_as_float((uint32_t)(a1 >> 32)) + bz.y);
            *reinterpret_cast<float2*>(out + (size_t)r0 * DIM + cj) = o0;
            *reinterpret_cast<float2*>(out + (size_t)(r0 + 8) * DIM + cj) = o1;
        }
    }
}

// ---------------- launch ----------------
extern "C" void kernel_launch(void* const* d_in, const int* in_sizes, int n_in,
                              void* d_out, int out_size) {
    const float* x    = (const float*)d_in[0];
    const float* w    = (const float*)d_in[1];
    const float* bias = (const float*)d_in[2];
    float* out = (float*)d_out;

    void *xq, *wq, *sx, *sw;
    cudaGetSymbolAddress(&xq, g_xq);
    cudaGetSymbolAddress(&wq, g_wq);
    cudaGetSymbolAddress(&sx, g_sx);
    cudaGetSymbolAddress(&sw, g_sw);

    cudaFuncSetAttribute(gemm_kernel, cudaFuncAttributeMaxDynamicSharedMemorySize, SMEM_TOT);

    const int nthreads = 2 * DIM * DIM / 4;         // 8 threads per 32-elem block, 2 tensors
    quant2_kernel<<<nthreads / 256, 256>>>(x, w, (uint8_t*)xq, (uint8_t*)wq,
                                           (float*)sx, (float*)sw);
    gemm_kernel<<<dim3(16, 16), 512, SMEM_TOT>>>(bias, out);
}

// round 7
// speedup vs baseline: 1.9216x; 1.1854x over previous
#include <cuda_runtime.h>
#include <cuda_fp8.h>
#include <cstdint>

#define DIM 2048
#define NB  (DIM / 32)   // 64 scale blocks per row

// ---------------- scratch (device globals: no allocation allowed) ----------------
__device__ uint8_t g_xq[DIM * DIM];   // x quantized e4m3
__device__ uint8_t g_wq[DIM * DIM];   // w quantized e4m3
__device__ float   g_sxT[NB * DIM];   // x block scales, TRANSPOSED [block][row]
__device__ float   g_swT[NB * DIM];   // w block scales, TRANSPOSED [block][row]

// ---------------- fused quantizer: 8 threads per 32-elem block ----------------
__global__ void __launch_bounds__(256) quant2_kernel(
        const float* __restrict__ x, const float* __restrict__ w) {
    const int gtid = blockIdx.x * blockDim.x + threadIdx.x;
    const int half = DIM * DIM / 4;                 // float4 count per tensor
    const bool isW = gtid >= half;
    const int t = isW ? gtid - half : gtid;
    const float4 v = (isW ? reinterpret_cast<const float4*>(w)
                          : reinterpret_cast<const float4*>(x))[t];
    float m = fmaxf(fmaxf(fabsf(v.x), fabsf(v.y)), fmaxf(fabsf(v.z), fabsf(v.w)));
    m = fmaxf(m, __shfl_xor_sync(0xFFFFFFFFu, m, 1));
    m = fmaxf(m, __shfl_xor_sync(0xFFFFFFFFu, m, 2));
    m = fmaxf(m, __shfl_xor_sync(0xFFFFFFFFu, m, 4));
    const float s = fmaxf(__fdiv_rn(m, 448.0f), 1e-30f);

    uint32_t pk = 0;
    const float e[4] = {v.x, v.y, v.z, v.w};
#pragma unroll
    for (int j = 0; j < 4; j++) {
        float qv = __fdiv_rn(e[j], s);              // RN div, matches jnp
        pk |= ((uint32_t)(uint8_t)__nv_cvt_float_to_fp8(qv, __NV_SATFINITE, __NV_E4M3)) << (8 * j);
    }
    reinterpret_cast<uint32_t*>(isW ? g_wq : g_xq)[t] = pk;
    if ((t & 7) == 0) {
        const int idx = t >> 3;                     // row-major block index
        const int row = idx >> 6, cb = idx & 63;    // NB = 64
        (isW ? g_swT : g_sxT)[cb * DIM + row] = s;
    }
}

// ---------------- GEMM: CTA 128x128, 16 warps of 32x32, 3-stage cp.async ----------------
// Stage: A 16KB | B 16KB | SX 2KB | SW 2KB => 36864 B; three stages = 110592 B.
static constexpr int STG      = 36864;
static constexpr int OFF_B    = 16384;
static constexpr int OFF_SX   = 32768;
static constexpr int OFF_SW   = 34816;
static constexpr int SMEM_TOT = 3 * STG;

#define SWZ_OFF(r, c) (((r) * 128) + ((((c) ^ ((r) & 7)) & 7) << 4))

__device__ __forceinline__ void cp16(uint32_t saddr, const void* gptr) {
    asm volatile("cp.async.cg.shared.global [%0], [%1], 16;"
                 :: "r"(saddr), "l"(__cvta_generic_to_global(gptr)));
}
__device__ __forceinline__ void cp16ca(uint32_t saddr, const void* gptr) {
    asm volatile("cp.async.ca.shared.global [%0], [%1], 16;"
                 :: "r"(saddr), "l"(__cvta_generic_to_global(gptr)));
}

__device__ __forceinline__ unsigned long long pk2(float lo, float hi) {
    unsigned long long r;
    asm("mov.b64 %0, {%1, %2};" : "=l"(r) : "f"(lo), "f"(hi));
    return r;
}
__device__ __forceinline__ unsigned long long mul2(unsigned long long a, unsigned long long b) {
    unsigned long long r;
    asm("mul.rn.f32x2 %0, %1, %2;" : "=l"(r) : "l"(a), "l"(b));
    return r;
}
__device__ __forceinline__ unsigned long long fma2(unsigned long long a, unsigned long long b,
                                                   unsigned long long c) {
    unsigned long long r;
    asm("fma.rn.f32x2 %0, %1, %2, %3;" : "=l"(r) : "l"(a), "l"(b), "l"(c));
    return r;
}

__global__ void __launch_bounds__(512, 1)
gemm_kernel(const float* __restrict__ bias, float* __restrict__ out) {
    extern __shared__ __align__(1024) char smem[];
    const uint32_t sbase = (uint32_t)__cvta_generic_to_shared(smem);
    const int tid  = threadIdx.x;
    const int lane = tid & 31, warp = tid >> 5;
    const int m0 = blockIdx.y * 128, n0 = blockIdx.x * 128;
    const int wm0 = (warp >> 2) * 32, wn0 = (warp & 3) * 32;   // 4x4 warp grid

    unsigned long long acc[2][4][2] = {};

    // ---- loader constants: each thread owns one row-chunk pair (32B contiguous) ----
    const int lr  = tid >> 2;
    const int lc0 = (tid & 3) * 2;
    const uint32_t aoff0 = SWZ_OFF(lr, lc0);
    const uint32_t aoff1 = SWZ_OFF(lr, lc0 + 1);
    const uint8_t* gA = g_xq + (size_t)(m0 + lr) * DIM + lc0 * 16;
    const uint8_t* gB = g_wq + (size_t)(n0 + lr) * DIM + lc0 * 16;
    const float* gS = nullptr;
    uint32_t soff = 0;
    if (tid < 128) {
        gS = g_sxT + (size_t)(tid >> 5) * DIM + m0 + (tid & 31) * 4;
        soff = OFF_SX + tid * 16;
    } else if (tid < 256) {
        const int t = tid - 128;
        gS = g_swT + (size_t)(t >> 5) * DIM + n0 + (t & 31) * 4;
        soff = OFF_SW + t * 16;
    }

    uint32_t woff = 0;
    auto load_stage = [&]() {
        const uint32_t sb = sbase + woff;
        cp16(sb + aoff0, gA);
        cp16(sb + aoff1, gA + 16);
        cp16(sb + OFF_B + aoff0, gB);
        cp16(sb + OFF_B + aoff1, gB + 16);
        gA += 128; gB += 128;
        if (tid < 256) { cp16ca(sb + soff, gS); gS += 4 * DIM; }
        woff = (woff == 2 * STG) ? 0u : woff + STG;
    };

    // ---- fragment base offsets (b enters only as XOR (b<<5)) ----
    const int mlm = lane >> 3;
    const int rA  = wm0 + (lane & 15);
    const uint32_t offA0 = SWZ_OFF(rA, (lane >> 4));
    const uint32_t offA1 = offA0 + 16 * 128;
    const int rB  = wn0 + ((mlm >> 1) << 3) + (lane & 7);
    const uint32_t offB0 = OFF_B + SWZ_OFF(rB, (mlm & 1));
    const uint32_t offB1 = offB0 + 16 * 128;
    const uint32_t offSX = OFF_SX + ((uint32_t)(wm0 + (lane >> 2)) << 2);
    const uint32_t offSW = OFF_SW + ((uint32_t)(wn0 + ((lane & 3) << 1)) << 2);

    load_stage();
    asm volatile("cp.async.commit_group;" ::: "memory");
    load_stage();
    asm volatile("cp.async.commit_group;" ::: "memory");

    uint32_t roff = 0;
#pragma unroll 1
    for (int kc = 0; kc < 16; kc++) {
        asm volatile("cp.async.wait_group 1;" ::: "memory");
        __syncthreads();
        if (kc < 14) load_stage();
        asm volatile("cp.async.commit_group;" ::: "memory");

        const uint32_t sb = sbase + roff;
        const char* ss = smem + roff;
        const uint32_t a0 = sb + offA0, a1 = sb + offA1;
        const uint32_t b0 = sb + offB0, b1 = sb + offB1;
        const char* px = ss + offSX;
        const char* pw = ss + offSW;

#pragma unroll
        for (int b = 0; b < 4; b++) {
            const uint32_t bx = (uint32_t)b << 5;
            uint32_t af[2][4];
            asm volatile("ldmatrix.sync.aligned.m8n8.x4.shared.b16 {%0,%1,%2,%3}, [%4];"
                         : "=r"(af[0][0]), "=r"(af[0][1]), "=r"(af[0][2]), "=r"(af[0][3])
                         : "r"(a0 ^ bx));
            asm volatile("ldmatrix.sync.aligned.m8n8.x4.shared.b16 {%0,%1,%2,%3}, [%4];"
                         : "=r"(af[1][0]), "=r"(af[1][1]), "=r"(af[1][2]), "=r"(af[1][3])
                         : "r"(a1 ^ bx));
            uint32_t bf[4][2];
            asm volatile("ldmatrix.sync.aligned.m8n8.x4.shared.b16 {%0,%1,%2,%3}, [%4];"
                         : "=r"(bf[0][0]), "=r"(bf[0][1]), "=r"(bf[1][0]), "=r"(bf[1][1])
                         : "r"(b0 ^ bx));
            asm volatile("ldmatrix.sync.aligned.m8n8.x4.shared.b16 {%0,%1,%2,%3}, [%4];"
                         : "=r"(bf[2][0]), "=r"(bf[2][1]), "=r"(bf[3][0]), "=r"(bf[3][1])
                         : "r"(b1 ^ bx));

            // scales: b-major smem layout => all offsets are immediates
            unsigned long long sxaa[2], sxbb[2], sw01[4];
#pragma unroll
            for (int mt = 0; mt < 2; mt++) {
                const float a  = *reinterpret_cast<const float*>(px + b * 512 + mt * 64);
                const float bb = *reinterpret_cast<const float*>(px + b * 512 + mt * 64 + 32);
                sxaa[mt] = pk2(a, a);
                sxbb[mt] = pk2(bb, bb);
            }
#pragma unroll
            for (int nt = 0; nt < 4; nt++) {
                const float2 v2 = *reinterpret_cast<const float2*>(pw + b * 512 + nt * 32);
                sw01[nt] = pk2(v2.x, v2.y);
            }

            // 8 independent mmas + f32x2 scale-apply
#pragma unroll
            for (int nt = 0; nt < 4; nt++)
#pragma unroll
                for (int mt = 0; mt < 2; mt++) {
                    float d0, d1, d2, d3;
                    asm volatile(
                        "mma.sync.aligned.m16n8k32.row.col.f32.e4m3.e4m3.f32 "
                        "{%0,%1,%2,%3}, {%4,%5,%6,%7}, {%8,%9}, {%10,%11,%12,%13};"
                        : "=f"(d0), "=f"(d1), "=f"(d2), "=f"(d3)
                        : "r"(af[mt][0]), "r"(af[mt][1]), "r"(af[mt][2]), "r"(af[mt][3]),
                          "r"(bf[nt][0]), "r"(bf[nt][1]),
                          "f"(0.f), "f"(0.f), "f"(0.f), "f"(0.f));
                    acc[mt][nt][0] = fma2(mul2(sxaa[mt], sw01[nt]), pk2(d0, d1), acc[mt][nt][0]);
                    acc[mt][nt][1] = fma2(mul2(sxbb[mt], sw01[nt]), pk2(d2, d3), acc[mt][nt][1]);
                }
        }
        roff = (roff == 2 * STG) ? 0u : roff + STG;
    }

    // ---- epilogue: add bias, store fp32 ----
#pragma unroll
    for (int mt = 0; mt < 2; mt++) {
        const int r0 = m0 + wm0 + mt * 16 + (lane >> 2);
#pragma unroll
        for (int nt = 0; nt < 4; nt++) {
            const int cj = n0 + wn0 + nt * 8 + ((lane & 3) << 1);
            const float2 bz = *reinterpret_cast<const float2*>(bias + cj);
            const unsigned long long a0 = acc[mt][nt][0], a1 = acc[mt][nt][1];
            float2 o0 = make_float2(__uint_as_float((uint32_t)a0) + bz.x,
                                    __uint_as_float((uint32_t)(a0 >> 32)) + bz.y);
            float2 o1 = make_float2(__uint_as_float((uint32_t)a1) + bz.x,
                                    __uint_as_float((uint32_t)(a1 >> 32)) + bz.y);
            *reinterpret_cast<float2*>(out + (size_t)r0 * DIM + cj) = o0;
            *reinterpret_cast<float2*>(out + (size_t)(r0 + 8) * DIM + cj) = o1;
        }
    }
}

// ---------------- launch ----------------
extern "C" void kernel_launch(void* const* d_in, const int* in_sizes, int n_in,
                              void* d_out, int out_size) {
    const float* x    = (const float*)d_in[0];
    const float* w    = (const float*)d_in[1];
    const float* bias = (const float*)d_in[2];
    float* out = (float*)d_out;

    cudaFuncSetAttribute(gemm_kernel, cudaFuncAttributeMaxDynamicSharedMemorySize, SMEM_TOT);

    const int nthreads = 2 * DIM * DIM / 4;         // one float4 per thread, 2 tensors
    quant2_kernel<<<nthreads / 256, 256>>>(x, w);
    gemm_kernel<<<dim3(16, 16), 512, SMEM_TOT>>>(bias, out);
}